// round 2
// baseline (speedup 1.0000x reference)
#include <cuda_runtime.h>
#include <math_constants.h>

// Problem constants (fixed shapes from reference)
#define N_VEC   65536           // 16*4096 vectors
#define D       64              // embedding dim
#define K       1024            // codebook size
#define TK      128             // codebook tile (smem): 128*64*4 = 32KB
#define NTILE   64              // vectors per block
#define NBLOCKS (N_VEC / NTILE) // 1024

// Output layout in d_out (flattened tuple, reference return order):
//   [0, 4194304)                      quantized_st  (f32)
//   [4194304, 4194304+67108864)       encodings     (f32 one-hot)
//   [71303168, 71303171)              loss, codebook_loss, commitment_loss
#define OUT_E_OFF  ((size_t)N_VEC * D)                 // 4194304
#define OUT_S_OFF  (OUT_E_OFF + (size_t)N_VEC * K)     // 71303168

__device__ float  g_B[K];          // ||e_k||^2 per code
__device__ double g_part[NBLOCKS]; // per-block loss partial sums

// ---------------------------------------------------------------------------
// Kernel 1: precompute ||e_k||^2 (mimics jnp.sum(embedding*embedding, axis=1))
// ---------------------------------------------------------------------------
__global__ void vq_prep_kernel(const float* __restrict__ emb) {
    int k = blockIdx.x * blockDim.x + threadIdx.x;
    if (k < K) {
        float b = 0.f;
        #pragma unroll
        for (int d = 0; d < D; d++) {
            float v = emb[k * D + d];
            b += v * v;
        }
        g_B[k] = b;
    }
}

// ---------------------------------------------------------------------------
// Kernel 2: main VQ — argmin over codebook with reference-rounding mimicry,
// then write quantized_st, one-hot encodings, and per-block loss partials.
// ---------------------------------------------------------------------------
__global__ __launch_bounds__(NTILE) void vq_main_kernel(
    const float* __restrict__ x_g,
    const float* __restrict__ emb,
    float* __restrict__ out)
{
    __shared__ float  sE[TK * D];   // 32KB codebook tile
    __shared__ float  sB[TK];
    __shared__ int    sIdx[NTILE];
    __shared__ double sRed[NTILE];

    const int tid = threadIdx.x;
    const int n0  = blockIdx.x * NTILE;
    const int n   = n0 + tid;

    // Load this thread's vector into registers (16x LDG.128)
    float x[D];
    {
        const float4* xg = reinterpret_cast<const float4*>(x_g + (size_t)n * D);
        #pragma unroll
        for (int j = 0; j < D / 4; j++) {
            float4 v = xg[j];
            x[4*j+0] = v.x; x[4*j+1] = v.y; x[4*j+2] = v.z; x[4*j+3] = v.w;
        }
    }

    // A = sum(x*x) — common across k; 1-ulp differences vs reference are a
    // uniform grid shift of all distances (same binade) => argmin-invariant.
    float A = 0.f;
    #pragma unroll
    for (int d = 0; d < D; d++) A = fmaf(x[d], x[d], A);

    float best = CUDART_INF_F;
    int   bidx = 0;

    for (int k0 = 0; k0 < K; k0 += TK) {
        __syncthreads();
        // Cooperative tile load (coalesced float4)
        {
            const float4* g4 = reinterpret_cast<const float4*>(emb + (size_t)k0 * D);
            float4* s4 = reinterpret_cast<float4*>(sE);
            #pragma unroll
            for (int i = tid; i < TK * D / 4; i += NTILE) s4[i] = g4[i];
            for (int i = tid; i < TK; i += NTILE) sB[i] = g_B[k0 + i];
        }
        __syncthreads();

        // 4 independent FMA chains (4 codes at a time) — broadcast LDS.128
        #pragma unroll 1
        for (int kk = 0; kk < TK; kk += 4) {
            const float4* e0 = reinterpret_cast<const float4*>(sE + (kk + 0) * D);
            const float4* e1 = reinterpret_cast<const float4*>(sE + (kk + 1) * D);
            const float4* e2 = reinterpret_cast<const float4*>(sE + (kk + 2) * D);
            const float4* e3 = reinterpret_cast<const float4*>(sE + (kk + 3) * D);
            float a0 = 0.f, a1 = 0.f, a2 = 0.f, a3 = 0.f;
            #pragma unroll
            for (int j = 0; j < D / 4; j++) {
                float4 v0 = e0[j], v1 = e1[j], v2 = e2[j], v3 = e3[j];
                // strictly ascending-d sequential accumulation per chain
                a0 = fmaf(x[4*j+0], v0.x, a0);
                a0 = fmaf(x[4*j+1], v0.y, a0);
                a0 = fmaf(x[4*j+2], v0.z, a0);
                a0 = fmaf(x[4*j+3], v0.w, a0);
                a1 = fmaf(x[4*j+0], v1.x, a1);
                a1 = fmaf(x[4*j+1], v1.y, a1);
                a1 = fmaf(x[4*j+2], v1.z, a1);
                a1 = fmaf(x[4*j+3], v1.w, a1);
                a2 = fmaf(x[4*j+0], v2.x, a2);
                a2 = fmaf(x[4*j+1], v2.y, a2);
                a2 = fmaf(x[4*j+2], v2.z, a2);
                a2 = fmaf(x[4*j+3], v2.w, a2);
                a3 = fmaf(x[4*j+0], v3.x, a3);
                a3 = fmaf(x[4*j+1], v3.y, a3);
                a3 = fmaf(x[4*j+2], v3.z, a3);
                a3 = fmaf(x[4*j+3], v3.w, a3);
            }
            // dist = fl(fl(A + B_k) - 2*dot)  (2*dot exact: single final rounding,
            // identical to the reference's fl(S) - fl(2C) then fl of the subtract)
            float s0 = A + sB[kk + 0];
            float s1 = A + sB[kk + 1];
            float s2 = A + sB[kk + 2];
            float s3 = A + sB[kk + 3];
            float d0 = s0 - 2.f * a0;
            float d1 = s1 - 2.f * a1;
            float d2 = s2 - 2.f * a2;
            float d3 = s3 - 2.f * a3;
            // ascending k, strict <  => first-occurrence min (jnp.argmin semantics)
            if (d0 < best) { best = d0; bidx = k0 + kk + 0; }
            if (d1 < best) { best = d1; bidx = k0 + kk + 1; }
            if (d2 < best) { best = d2; bidx = k0 + kk + 2; }
            if (d3 < best) { best = d3; bidx = k0 + kk + 3; }
        }
    }

    sIdx[tid] = bidx;
    __syncthreads();

    // quantized_st + loss partials (coalesced; mimic fl(x + fl(q - x)))
    double lsum = 0.0;
    #pragma unroll 1
    for (int i = tid; i < NTILE * D; i += NTILE) {
        int r = i >> 6;          // row within tile (D = 64)
        int d = i & (D - 1);
        int idx = sIdx[r];
        float q  = emb[idx * D + d];
        float xx = x_g[(size_t)(n0 + r) * D + d];
        float diff = q - xx;                 // fl(q - x)
        float qst  = xx + diff;              // fl(x + fl(q - x)) — do NOT fold to q
        out[(size_t)(n0 + r) * D + d] = qst;
        float t = diff * diff;               // fl32 square, then wide accumulate
        lsum += (double)t;
    }
    sRed[tid] = lsum;
    __syncthreads();
    #pragma unroll
    for (int s = NTILE / 2; s > 0; s >>= 1) {
        if (tid < s) sRed[tid] += sRed[tid + s];
        __syncthreads();
    }
    if (tid == 0) g_part[blockIdx.x] = sRed[0];

    // encodings: write the full one-hot rows directly (covers 0xAA poison)
    float* eout = out + OUT_E_OFF;
    #pragma unroll 1
    for (int i = tid; i < NTILE * (K / 4); i += NTILE) {
        int r  = i >> 8;         // K/4 = 256 float4 per row
        int c4 = i & 255;
        int idx = sIdx[r];
        float4 v = make_float4(0.f, 0.f, 0.f, 0.f);
        if ((idx >> 2) == c4) {
            reinterpret_cast<float*>(&v)[idx & 3] = 1.f;
        }
        reinterpret_cast<float4*>(eout + (size_t)(n0 + r) * K)[c4] = v;
    }
}

// ---------------------------------------------------------------------------
// Kernel 3: deterministic final loss reduction + scalar outputs
// ---------------------------------------------------------------------------
__global__ void vq_finalize_kernel(float* __restrict__ out) {
    __shared__ double sR[256];
    int tid = threadIdx.x;
    double s = 0.0;
    for (int i = tid; i < NBLOCKS; i += 256) s += g_part[i];
    sR[tid] = s;
    __syncthreads();
    #pragma unroll
    for (int st = 128; st > 0; st >>= 1) {
        if (tid < st) sR[tid] += sR[tid + st];
        __syncthreads();
    }
    if (tid == 0) {
        float cb = (float)(sR[0] / (double)((size_t)N_VEC * D)); // codebook_loss
        float cm = cb;                                           // commitment_loss (identical forward)
        float loss = cb + 0.25f * cm;
        out[OUT_S_OFF + 0] = loss;
        out[OUT_S_OFF + 1] = cb;
        out[OUT_S_OFF + 2] = cm;
    }
}

// ---------------------------------------------------------------------------
extern "C" void kernel_launch(void* const* d_in, const int* in_sizes, int n_in,
                              void* d_out, int out_size) {
    const float* x   = (const float*)d_in[0];  // inputs [16,4096,64] f32
    const float* emb = (const float*)d_in[1];  // embedding [1024,64] f32
    float* out = (float*)d_out;

    vq_prep_kernel<<<1, K>>>(emb);
    vq_main_kernel<<<NBLOCKS, NTILE>>>(x, emb, out);
    vq_finalize_kernel<<<1, 256>>>(out);
}

// round 4
// speedup vs baseline: 1.7193x; 1.7193x over previous
#include <cuda_runtime.h>
#include <cuda_bf16.h>
#include <cstdint>
#include <math_constants.h>

#define N_VEC 65536
#define D 64
#define K 1024
#define MTILE 512
#define NBLK (N_VEC / MTILE)       // 128
#define MARGIN 4e-4f
#define OUT_E_OFF ((size_t)N_VEC * D)
#define OUT_S_OFF (OUT_E_OFF + (size_t)N_VEC * K)

#define APAD 72                    // bf16 elems per padded row (144B)
#define BPAD 72
// dynamic smem offsets (bytes)
#define OFF_SB  0                  // 4KB  : g_B copy
#define OFF_IDX 4096               // 2KB  : per-row argmin
#define OFF_A   6144               // 512*144 = 73728
#define OFF_B   79872              // 1024*144 = 147456
#define SMEM_TOTAL 227328

__device__ float  g_B[K];
__device__ __align__(16) __nv_bfloat16 g_ebf[K * BPAD];
__device__ int    g_cnt;
__device__ int    g_list[N_VEC];
__device__ double g_loss[N_VEC];

// descending top-4 insert (s0 best). S,I are float[4]/int[4] (const-indexed).
#define INS4(S, I, s, i) { if ((s) > S[3]) { \
    if ((s) > S[2]) { S[3]=S[2]; I[3]=I[2]; \
        if ((s) > S[1]) { S[2]=S[1]; I[2]=I[1]; \
            if ((s) > S[0]) { S[1]=S[0]; I[1]=I[0]; S[0]=(s); I[0]=(i); } \
            else { S[1]=(s); I[1]=(i); } } \
        else { S[2]=(s); I[2]=(i); } } \
    else { S[3]=(s); I[3]=(i); } } }

#define MMA(c, a, bb0, bb1) asm volatile( \
    "mma.sync.aligned.m16n8k16.row.col.f32.bf16.bf16.f32 " \
    "{%0,%1,%2,%3}, {%4,%5,%6,%7}, {%8,%9}, {%0,%1,%2,%3};" \
    : "+f"(c[0]), "+f"(c[1]), "+f"(c[2]), "+f"(c[3]) \
    : "r"(a[0]), "r"(a[1]), "r"(a[2]), "r"(a[3]), "r"(bb0), "r"(bb1))

#define CSWP(a, b) { if ((a) > (b)) { int _t = (a); (a) = (b); (b) = _t; } }

// ---------------- prep: g_B (exact chain) + padded bf16 codebook ----------
__global__ void vq_prep(const float* __restrict__ emb) {
    int k = blockIdx.x * blockDim.x + threadIdx.x;    // 8 x 128 = 1024
    float v[D];
    const float4* r4 = (const float4*)(emb + (size_t)k * D);
    #pragma unroll
    for (int j = 0; j < 16; j++) {
        float4 t = r4[j];
        v[4*j] = t.x; v[4*j+1] = t.y; v[4*j+2] = t.z; v[4*j+3] = t.w;
    }
    float bb = 0.f;
    #pragma unroll
    for (int d = 0; d < D; d++) bb += v[d] * v[d];
    g_B[k] = bb;
    __nv_bfloat162* eb = (__nv_bfloat162*)(g_ebf + (size_t)k * BPAD);
    #pragma unroll
    for (int j = 0; j < 32; j++)
        eb[j] = __float22bfloat162_rn(make_float2(v[2*j], v[2*j+1]));
    #pragma unroll
    for (int j = 32; j < 36; j++)
        eb[j] = __float22bfloat162_rn(make_float2(0.f, 0.f));
    if (k == 0) g_cnt = 0;
}

// ---------------- main: HMMA prefilter + top4 + exact rescore -------------
__global__ __launch_bounds__(256, 1) void vq_main(
    const float* __restrict__ xg, const float* __restrict__ emb, float* __restrict__ out)
{
    extern __shared__ char sm[];
    float*    sB   = (float*)(sm + OFF_SB);
    int*      sIdx = (int*)(sm + OFF_IDX);
    uint32_t* Aw   = (uint32_t*)(sm + OFF_A);   // 36 words per row
    uint32_t* Bw   = (uint32_t*)(sm + OFF_B);

    const int tid = threadIdx.x;
    const int warp = tid >> 5, lane = tid & 31;
    const int g = lane >> 2, tig = lane & 3;
    const int n0 = blockIdx.x * MTILE;

    for (int i = tid; i < K; i += 256) sB[i] = g_B[i];
    { // stage A: x f32 -> bf16 padded rows
        const float4* x4 = (const float4*)(xg + (size_t)n0 * D);
        for (int i = tid; i < MTILE * 16; i += 256) {
            float4 v = x4[i];
            int row = i >> 4, j = i & 15;
            __nv_bfloat162* p =
                (__nv_bfloat162*)((__nv_bfloat16*)(sm + OFF_A) + row * APAD + j * 4);
            p[0] = __float22bfloat162_rn(make_float2(v.x, v.y));
            p[1] = __float22bfloat162_rn(make_float2(v.z, v.w));
        }
    }
    { // stage B: padded bf16 codebook copy
        const float4* e4 = (const float4*)g_ebf;
        float4* s4 = (float4*)(sm + OFF_B);
        for (int i = tid; i < (K * BPAD * 2) / 16; i += 256) s4[i] = e4[i];
    }
    __syncthreads();

    for (int pass = 0; pass < 2; pass++) {
        const int rbase = pass * 256 + warp * 32;
        // preload A fragments: [rowtile][kstep][4 regs]
        uint32_t af[2][4][4];
        #pragma unroll
        for (int rt = 0; rt < 2; rt++) {
            int r0w = (rbase + rt * 16 + g) * 36;
            #pragma unroll
            for (int ks = 0; ks < 4; ks++) {
                int kw = ks * 8 + tig;
                af[rt][ks][0] = Aw[r0w + kw];
                af[rt][ks][1] = Aw[r0w + 288 + kw];      // +8 rows
                af[rt][ks][2] = Aw[r0w + kw + 4];
                af[rt][ks][3] = Aw[r0w + 288 + kw + 4];
            }
        }
        float TS[4][4]; int TI[4][4];
        #pragma unroll
        for (int j = 0; j < 4; j++)
            #pragma unroll
            for (int p = 0; p < 4; p++) { TS[j][p] = -CUDART_INF_F; TI[j][p] = 0; }

        for (int nt = 0; nt < 128; nt++) {
            const int nbase = nt * 8;
            uint32_t b0[4], b1[4];
            const int brw = (nbase + g) * 36;
            #pragma unroll
            for (int ks = 0; ks < 4; ks++) {
                b0[ks] = Bw[brw + ks * 8 + tig];
                b1[ks] = Bw[brw + ks * 8 + tig + 4];
            }
            float c0[4] = {0.f,0.f,0.f,0.f}, c1[4] = {0.f,0.f,0.f,0.f};
            #pragma unroll
            for (int ks = 0; ks < 4; ks++) {
                MMA(c0, af[0][ks], b0[ks], b1[ks]);
                MMA(c1, af[1][ks], b0[ks], b1[ks]);
            }
            const int k0i = nbase + tig * 2;
            const float Bc0 = sB[k0i], Bc1 = sB[k0i + 1];
            float s;
            s = fmaf(2.f, c0[0], -Bc0); INS4(TS[0], TI[0], s, k0i);
            s = fmaf(2.f, c0[1], -Bc1); INS4(TS[0], TI[0], s, k0i + 1);
            s = fmaf(2.f, c0[2], -Bc0); INS4(TS[1], TI[1], s, k0i);
            s = fmaf(2.f, c0[3], -Bc1); INS4(TS[1], TI[1], s, k0i + 1);
            s = fmaf(2.f, c1[0], -Bc0); INS4(TS[2], TI[2], s, k0i);
            s = fmaf(2.f, c1[1], -Bc1); INS4(TS[2], TI[2], s, k0i + 1);
            s = fmaf(2.f, c1[2], -Bc0); INS4(TS[3], TI[3], s, k0i);
            s = fmaf(2.f, c1[3], -Bc1); INS4(TS[3], TI[3], s, k0i + 1);
        }
        // quad merge (lanes in a quad own the same 4 rows, disjoint cols)
        #pragma unroll
        for (int dd = 1; dd <= 2; dd <<= 1) {
            #pragma unroll
            for (int j = 0; j < 4; j++) {
                float ns[4]; int ni[4];
                #pragma unroll
                for (int p = 0; p < 4; p++) {
                    ns[p] = __shfl_xor_sync(0xffffffffu, TS[j][p], dd);
                    ni[p] = __shfl_xor_sync(0xffffffffu, TI[j][p], dd);
                }
                #pragma unroll
                for (int p = 0; p < 4; p++) INS4(TS[j], TI[j], ns[p], ni[p]);
            }
        }
        // this thread owns row slot j == tig  (row = g + tig*8 within warp)
        const int rowp = warp * 32 + g + tig * 8;
        const int n = n0 + pass * 256 + rowp;
        float cs[4]; int ci[4];
        #pragma unroll
        for (int j = 0; j < 4; j++) if (tig == j) {
            #pragma unroll
            for (int p = 0; p < 4; p++) { cs[p] = TS[j][p]; ci[p] = TI[j][p]; }
        }
        const bool fb = (cs[3] >= cs[0] - MARGIN);
        CSWP(ci[0], ci[1]); CSWP(ci[2], ci[3]);
        CSWP(ci[0], ci[2]); CSWP(ci[1], ci[3]); CSWP(ci[1], ci[2]);

        // exact rescore (validated round-0 fl chain, ascending-k strict <)
        float xv[64];
        {
            const float4* xr = (const float4*)(xg + (size_t)n * D);
            #pragma unroll
            for (int j = 0; j < 16; j++) {
                float4 v = xr[j];
                xv[4*j] = v.x; xv[4*j+1] = v.y; xv[4*j+2] = v.z; xv[4*j+3] = v.w;
            }
        }
        float Av = 0.f;
        #pragma unroll
        for (int d = 0; d < D; d++) Av = fmaf(xv[d], xv[d], Av);
        float best = CUDART_INF_F; int bidx = 0;
        #pragma unroll
        for (int q = 0; q < 4; q++) {
            int idx = ci[q];
            const float4* er = (const float4*)(emb + (size_t)idx * D);
            float a = 0.f;
            #pragma unroll
            for (int j = 0; j < 16; j++) {
                float4 v = er[j];
                a = fmaf(xv[4*j],   v.x, a);
                a = fmaf(xv[4*j+1], v.y, a);
                a = fmaf(xv[4*j+2], v.z, a);
                a = fmaf(xv[4*j+3], v.w, a);
            }
            float ddv = (Av + sB[idx]) - 2.f * a;
            if (ddv < best) { best = ddv; bidx = idx; }
        }
        if (fb) { int sl = atomicAdd(&g_cnt, 1); g_list[sl] = n; }
        sIdx[pass * 256 + rowp] = bidx;

        // quantized_st + per-vector loss (exact fl(x + fl(q-x)))
        {
            const float4* er = (const float4*)(emb + (size_t)bidx * D);
            float4* qo = (float4*)(out + (size_t)n * D);
            double ls = 0.0;
            #pragma unroll
            for (int j = 0; j < 16; j++) {
                float4 e4 = er[j];
                float dx = e4.x - xv[4*j],   dy = e4.y - xv[4*j+1];
                float dz = e4.z - xv[4*j+2], dw = e4.w - xv[4*j+3];
                qo[j] = make_float4(xv[4*j]+dx, xv[4*j+1]+dy, xv[4*j+2]+dz, xv[4*j+3]+dw);
                ls += (double)(dx*dx) + (double)(dy*dy) + (double)(dz*dz) + (double)(dw*dw);
            }
            g_loss[n] = ls;
        }
        __syncthreads();
        // one-hot encodings for this pass (coalesced float4)
        float* eout = out + OUT_E_OFF;
        for (int i = tid; i < 256 * 256; i += 256) {
            int r = i >> 8, c4 = i & 255;
            int idx = sIdx[pass * 256 + r];
            float4 v = make_float4(0.f, 0.f, 0.f, 0.f);
            if ((idx >> 2) == c4) ((float*)&v)[idx & 3] = 1.f;
            ((float4*)(eout + (size_t)(n0 + pass * 256 + r) * K))[c4] = v;
        }
        __syncthreads();
    }
}

// ---------------- fallback: exact full scan, chunked smem codebook --------
#define FCHUNK 128
__global__ __launch_bounds__(256) void vq_fallback(
    const float* __restrict__ xg, const float* __restrict__ emb, float* __restrict__ out)
{
    __shared__ float sC[FCHUNK * 66];   // 33792B
    const int cnt = g_cnt;
    if (blockIdx.x * 8 >= cnt) return;
    const int tid = threadIdx.x, warp = tid >> 5, lane = tid & 31;
    const int nwg = gridDim.x * 8;
    const int rounds = (cnt + nwg - 1) / nwg;
    for (int rd = 0; rd < rounds; rd++) {
        const int it = rd * nwg + blockIdx.x * 8 + warp;
        const bool act = it < cnt;
        const int n = act ? g_list[it] : 0;
        float xv[64];
        float Av = 0.f;
        if (act) {
            const float4* xr = (const float4*)(xg + (size_t)n * D);
            #pragma unroll
            for (int j = 0; j < 16; j++) {
                float4 v = xr[j];
                xv[4*j] = v.x; xv[4*j+1] = v.y; xv[4*j+2] = v.z; xv[4*j+3] = v.w;
            }
            #pragma unroll
            for (int d = 0; d < D; d++) Av = fmaf(xv[d], xv[d], Av);
        }
        float best = CUDART_INF_F; int bidx = 0;
        for (int ch = 0; ch < K / FCHUNK; ch++) {
            __syncthreads();
            const float4* e4 = (const float4*)(emb + (size_t)ch * FCHUNK * D);
            for (int i = tid; i < FCHUNK * 16; i += 256) {
                float4 v = e4[i];
                int row = i >> 4, j = i & 15;
                float* p = sC + row * 66 + j * 4;
                ((float2*)p)[0] = make_float2(v.x, v.y);
                ((float2*)p)[1] = make_float2(v.z, v.w);
            }
            __syncthreads();
            if (act) {
                for (int cj = 0; cj < FCHUNK / 32; cj++) {
                    int c = lane + cj * 32;
                    int k = ch * FCHUNK + c;
                    const float2* er = (const float2*)(sC + c * 66);
                    float a = 0.f;
                    #pragma unroll
                    for (int j = 0; j < 32; j++) {
                        float2 v = er[j];
                        a = fmaf(xv[2*j],   v.x, a);
                        a = fmaf(xv[2*j+1], v.y, a);
                    }
                    float ddv = (Av + g_B[k]) - 2.f * a;
                    if (ddv < best) { best = ddv; bidx = k; }
                }
            }
        }
        if (act) {
            unsigned long long key =
                ((unsigned long long)__float_as_uint(best) << 32) | (unsigned)bidx;
            #pragma unroll
            for (int o = 16; o; o >>= 1) {
                unsigned long long k2 = __shfl_down_sync(0xffffffffu, key, o);
                if (k2 < key) key = k2;
            }
            key = __shfl_sync(0xffffffffu, key, 0);
            int idx = (int)(key & 0xffffffffu);
            double ls = 0.0;
            if (lane < 16) {
                float4 e4 = ((const float4*)(emb + (size_t)idx * D))[lane];
                float4 xw = ((const float4*)(xg + (size_t)n * D))[lane];
                float dx = e4.x-xw.x, dy = e4.y-xw.y, dz = e4.z-xw.z, dw = e4.w-xw.w;
                ((float4*)(out + (size_t)n * D))[lane] =
                    make_float4(xw.x+dx, xw.y+dy, xw.z+dz, xw.w+dw);
                ls = (double)(dx*dx) + (double)(dy*dy) + (double)(dz*dz) + (double)(dw*dw);
            }
            #pragma unroll
            for (int o = 16; o; o >>= 1) ls += __shfl_down_sync(0xffffffffu, ls, o);
            if (lane == 0) g_loss[n] = ls;
            float* er = out + OUT_E_OFF + (size_t)n * K;
            for (int c4 = lane; c4 < 256; c4 += 32) {
                float4 v = make_float4(0.f, 0.f, 0.f, 0.f);
                if ((idx >> 2) == c4) ((float*)&v)[idx & 3] = 1.f;
                ((float4*)er)[c4] = v;
            }
        }
    }
}

// ---------------- finalize ------------------------------------------------
__global__ void vq_finalize(float* __restrict__ out) {
    __shared__ double sR[256];
    int tid = threadIdx.x;
    double s = 0.0;
    for (int i = tid; i < N_VEC; i += 256) s += g_loss[i];
    sR[tid] = s;
    __syncthreads();
    #pragma unroll
    for (int st = 128; st; st >>= 1) {
        if (tid < st) sR[tid] += sR[tid + st];
        __syncthreads();
    }
    if (tid == 0) {
        float cb = (float)(sR[0] / (double)((size_t)N_VEC * D));
        out[OUT_S_OFF + 0] = cb + 0.25f * cb;
        out[OUT_S_OFF + 1] = cb;
        out[OUT_S_OFF + 2] = cb;
    }
}

extern "C" void kernel_launch(void* const* d_in, const int* in_sizes, int n_in,
                              void* d_out, int out_size) {
    const float* x   = (const float*)d_in[0];
    const float* emb = (const float*)d_in[1];
    float* out = (float*)d_out;
    cudaFuncSetAttribute(vq_main, cudaFuncAttributeMaxDynamicSharedMemorySize, SMEM_TOTAL);
    vq_prep<<<8, 128>>>(emb);
    vq_main<<<NBLK, 256, SMEM_TOTAL>>>(x, emb, out);
    vq_fallback<<<148, 256>>>(x, emb, out);
    vq_finalize<<<1, 256>>>(out);
}

// round 5
// speedup vs baseline: 2.2422x; 1.3042x over previous
#include <cuda_runtime.h>
#include <cuda_bf16.h>
#include <cstdint>
#include <math_constants.h>

#define N_VEC 65536
#define D 64
#define K 1024
#define MTILE 512
#define NBLK (N_VEC / MTILE)       // 128
#define MARGIN 4e-4f
#define OUT_E_OFF ((size_t)N_VEC * D)
#define OUT_S_OFF (OUT_E_OFF + (size_t)N_VEC * K)

#define APAD 72                    // bf16 elems per padded row (144B)
#define BPAD 72
// dynamic smem offsets (bytes)
#define OFF_SB  0                  // 4KB : g_B copy
#define OFF_IDX 4096               // 2KB : per-row argmin
#define OFF_RED 6144               // 64B : per-warp loss partials
#define OFF_A   6272               // 512*144 = 73728
#define OFF_B   80000              // 1024*144 = 147456
#define SMEM_TOTAL 227456

__device__ float  g_B[K];
__device__ __align__(16) __nv_bfloat16 g_ebf[K * BPAD];
__device__ int    g_cnt;
__device__ int    g_list[N_VEC];
__device__ int    g_idx[N_VEC];
__device__ float  g_part[NBLK];
__device__ float  g_fix;

// descending top-4 insert (S[0] best). strict > keeps earlier (lower-k) on ties.
#define INS4(S, I, s, i) { if ((s) > S[3]) { \
    if ((s) > S[2]) { S[3]=S[2]; I[3]=I[2]; \
        if ((s) > S[1]) { S[2]=S[1]; I[2]=I[1]; \
            if ((s) > S[0]) { S[1]=S[0]; I[1]=I[0]; S[0]=(s); I[0]=(i); } \
            else { S[1]=(s); I[1]=(i); } } \
        else { S[2]=(s); I[2]=(i); } } \
    else { S[3]=(s); I[3]=(i); } } }

#define MMA(c, a, bb0, bb1) asm volatile( \
    "mma.sync.aligned.m16n8k16.row.col.f32.bf16.bf16.f32 " \
    "{%0,%1,%2,%3}, {%4,%5,%6,%7}, {%8,%9}, {%0,%1,%2,%3};" \
    : "+f"(c[0]), "+f"(c[1]), "+f"(c[2]), "+f"(c[3]) \
    : "r"(a[0]), "r"(a[1]), "r"(a[2]), "r"(a[3]), "r"(bb0), "r"(bb1))

#define CSWP(a, b) { if ((a) > (b)) { int _t = (a); (a) = (b); (b) = _t; } }

// ---------------- prep: g_B (exact chain) + padded bf16 codebook ----------
__global__ void vq_prep(const float* __restrict__ emb) {
    int k = blockIdx.x * blockDim.x + threadIdx.x;    // 8 x 128 = 1024
    float v[D];
    const float4* r4 = (const float4*)(emb + (size_t)k * D);
    #pragma unroll
    for (int j = 0; j < 16; j++) {
        float4 t = r4[j];
        v[4*j] = t.x; v[4*j+1] = t.y; v[4*j+2] = t.z; v[4*j+3] = t.w;
    }
    float bb = 0.f;
    #pragma unroll
    for (int d = 0; d < D; d++) bb += v[d] * v[d];
    g_B[k] = bb;
    __nv_bfloat162* eb = (__nv_bfloat162*)(g_ebf + (size_t)k * BPAD);
    #pragma unroll
    for (int j = 0; j < 32; j++)
        eb[j] = __float22bfloat162_rn(make_float2(v[2*j], v[2*j+1]));
    #pragma unroll
    for (int j = 32; j < 36; j++)
        eb[j] = __float22bfloat162_rn(make_float2(0.f, 0.f));
    if (k == 0) { g_cnt = 0; g_fix = 0.f; }
}

// ---------------- main: HMMA prefilter + top4 + exact rescore -------------
__global__ __launch_bounds__(512, 1) void vq_main(
    const float* __restrict__ xg, const float* __restrict__ emb, float* __restrict__ out)
{
    extern __shared__ char sm[];
    float*    sB   = (float*)(sm + OFF_SB);
    int*      sIdx = (int*)(sm + OFF_IDX);
    float*    sW   = (float*)(sm + OFF_RED);
    uint32_t* Aw   = (uint32_t*)(sm + OFF_A);   // 36 words per padded row
    uint32_t* Bw   = (uint32_t*)(sm + OFF_B);

    const int tid = threadIdx.x;
    const int warp = tid >> 5, lane = tid & 31;
    const int g = lane >> 2, tig = lane & 3;
    const int n0 = blockIdx.x * MTILE;

    for (int i = tid; i < K; i += 512) sB[i] = g_B[i];
    { // stage A: x f32 -> bf16 padded rows
        const float4* x4 = (const float4*)(xg + (size_t)n0 * D);
        for (int i = tid; i < MTILE * 16; i += 512) {
            float4 v = x4[i];
            int row = i >> 4, j = i & 15;
            __nv_bfloat162* p =
                (__nv_bfloat162*)((__nv_bfloat16*)(sm + OFF_A) + row * APAD + j * 4);
            p[0] = __float22bfloat162_rn(make_float2(v.x, v.y));
            p[1] = __float22bfloat162_rn(make_float2(v.z, v.w));
        }
    }
    { // stage B: padded bf16 codebook copy
        const float4* e4 = (const float4*)g_ebf;
        float4* s4 = (float4*)(sm + OFF_B);
        for (int i = tid; i < (K * BPAD * 2) / 16; i += 512) s4[i] = e4[i];
    }
    __syncthreads();

    const int rbase = warp * 32;
    // preload A fragments: [rowtile][kstep][4 regs]
    uint32_t af[2][4][4];
    #pragma unroll
    for (int rt = 0; rt < 2; rt++) {
        int r0w = (rbase + rt * 16 + g) * 36;
        #pragma unroll
        for (int ks = 0; ks < 4; ks++) {
            int kw = ks * 8 + tig;
            af[rt][ks][0] = Aw[r0w + kw];
            af[rt][ks][1] = Aw[r0w + 288 + kw];      // +8 rows
            af[rt][ks][2] = Aw[r0w + kw + 4];
            af[rt][ks][3] = Aw[r0w + 288 + kw + 4];
        }
    }
    float TS[4][4]; int TI[4][4];
    #pragma unroll
    for (int j = 0; j < 4; j++)
        #pragma unroll
        for (int p = 0; p < 4; p++) { TS[j][p] = -CUDART_INF_F; TI[j][p] = 0; }

    for (int nt = 0; nt < 128; nt++) {
        const int nbase = nt * 8;
        uint32_t b0[4], b1[4];
        const int brw = (nbase + g) * 36;
        #pragma unroll
        for (int ks = 0; ks < 4; ks++) {
            b0[ks] = Bw[brw + ks * 8 + tig];
            b1[ks] = Bw[brw + ks * 8 + tig + 4];
        }
        float c0[4] = {0.f,0.f,0.f,0.f}, c1[4] = {0.f,0.f,0.f,0.f};
        #pragma unroll
        for (int ks = 0; ks < 4; ks++) {
            MMA(c0, af[0][ks], b0[ks], b1[ks]);
            MMA(c1, af[1][ks], b0[ks], b1[ks]);
        }
        const int k0i = nbase + tig * 2;
        const float Bc0 = sB[k0i], Bc1 = sB[k0i + 1];
        // scores (proxy = 2*dot - ||e||^2); gated inserts (gate skips only no-ops)
        {
            float sa = fmaf(2.f, c0[0], -Bc0), sb2 = fmaf(2.f, c0[1], -Bc1);
            if (fmaxf(sa, sb2) > TS[0][3]) { INS4(TS[0], TI[0], sa, k0i); INS4(TS[0], TI[0], sb2, k0i+1); }
        }
        {
            float sa = fmaf(2.f, c0[2], -Bc0), sb2 = fmaf(2.f, c0[3], -Bc1);
            if (fmaxf(sa, sb2) > TS[1][3]) { INS4(TS[1], TI[1], sa, k0i); INS4(TS[1], TI[1], sb2, k0i+1); }
        }
        {
            float sa = fmaf(2.f, c1[0], -Bc0), sb2 = fmaf(2.f, c1[1], -Bc1);
            if (fmaxf(sa, sb2) > TS[2][3]) { INS4(TS[2], TI[2], sa, k0i); INS4(TS[2], TI[2], sb2, k0i+1); }
        }
        {
            float sa = fmaf(2.f, c1[2], -Bc0), sb2 = fmaf(2.f, c1[3], -Bc1);
            if (fmaxf(sa, sb2) > TS[3][3]) { INS4(TS[3], TI[3], sa, k0i); INS4(TS[3], TI[3], sb2, k0i+1); }
        }
    }
    // quad merge (lanes in a quad own the same 4 rows, disjoint cols)
    #pragma unroll
    for (int dd = 1; dd <= 2; dd <<= 1) {
        #pragma unroll
        for (int j = 0; j < 4; j++) {
            float ns[4]; int ni[4];
            #pragma unroll
            for (int p = 0; p < 4; p++) {
                ns[p] = __shfl_xor_sync(0xffffffffu, TS[j][p], dd);
                ni[p] = __shfl_xor_sync(0xffffffffu, TI[j][p], dd);
            }
            #pragma unroll
            for (int p = 0; p < 4; p++) INS4(TS[j], TI[j], ns[p], ni[p]);
        }
    }
    // this thread owns row slot j == tig  (row = g + tig*8 within warp)
    const int rowp = rbase + g + tig * 8;
    const int n = n0 + rowp;
    float cs[4]; int ci[4];
    #pragma unroll
    for (int j = 0; j < 4; j++) if (tig == j) {
        #pragma unroll
        for (int p = 0; p < 4; p++) { cs[p] = TS[j][p]; ci[p] = TI[j][p]; }
    }
    const bool fb = (cs[3] >= cs[0] - MARGIN);
    CSWP(ci[0], ci[1]); CSWP(ci[2], ci[3]);
    CSWP(ci[0], ci[2]); CSWP(ci[1], ci[3]); CSWP(ci[1], ci[2]);

    // exact rescore (validated round-0 fl chain, ascending-k strict <)
    float xv[64];
    {
        const float4* xr = (const float4*)(xg + (size_t)n * D);
        #pragma unroll
        for (int j = 0; j < 16; j++) {
            float4 v = xr[j];
            xv[4*j] = v.x; xv[4*j+1] = v.y; xv[4*j+2] = v.z; xv[4*j+3] = v.w;
        }
    }
    float Av = 0.f;
    #pragma unroll
    for (int d = 0; d < D; d++) Av = fmaf(xv[d], xv[d], Av);
    float best = CUDART_INF_F; int bidx = 0;
    #pragma unroll
    for (int q = 0; q < 4; q++) {
        int idx = ci[q];
        const float4* er = (const float4*)(emb + (size_t)idx * D);
        float a = 0.f;
        #pragma unroll
        for (int j = 0; j < 16; j++) {
            float4 v = er[j];
            a = fmaf(xv[4*j],   v.x, a);
            a = fmaf(xv[4*j+1], v.y, a);
            a = fmaf(xv[4*j+2], v.z, a);
            a = fmaf(xv[4*j+3], v.w, a);
        }
        float ddv = (Av + sB[idx]) - 2.f * a;
        if (ddv < best) { best = ddv; bidx = idx; }
    }
    if (fb) { int sl = atomicAdd(&g_cnt, 1); g_list[sl] = n; }
    sIdx[rowp] = bidx;
    g_idx[n] = bidx;

    // quantized_st + per-vector loss, all-FLOAT accumulation
    float ls = 0.f;
    {
        const float4* er = (const float4*)(emb + (size_t)bidx * D);
        float4* qo = (float4*)(out + (size_t)n * D);
        #pragma unroll
        for (int j = 0; j < 16; j++) {
            float4 e4 = er[j];
            float dx = e4.x - xv[4*j],   dy = e4.y - xv[4*j+1];
            float dz = e4.z - xv[4*j+2], dw = e4.w - xv[4*j+3];
            qo[j] = make_float4(xv[4*j]+dx, xv[4*j+1]+dy, xv[4*j+2]+dz, xv[4*j+3]+dw);
            ls += dx*dx + dy*dy + dz*dz + dw*dw;
        }
    }
    // block loss reduction: intra-warp shfl, then warp leaders
    #pragma unroll
    for (int o = 16; o; o >>= 1) ls += __shfl_down_sync(0xffffffffu, ls, o);
    if (lane == 0) sW[warp] = ls;
    __syncthreads();
    if (tid == 0) {
        float s = 0.f;
        #pragma unroll
        for (int w = 0; w < 16; w++) s += sW[w];
        g_part[blockIdx.x] = s;
    }

    // one-hot encodings (coalesced float4)
    float* eout = out + OUT_E_OFF;
    for (int i = tid; i < MTILE * 256; i += 512) {
        int r = i >> 8, c4 = i & 255;
        int idx = sIdx[r];
        float4 v = make_float4(0.f, 0.f, 0.f, 0.f);
        if ((idx >> 2) == c4) ((float*)&v)[idx & 3] = 1.f;
        ((float4*)(eout + (size_t)(n0 + r) * K))[c4] = v;
    }
}

// ---------------- fallback: exact full scan, chunked smem codebook --------
#define FCHUNK 128
__global__ __launch_bounds__(256) void vq_fallback(
    const float* __restrict__ xg, const float* __restrict__ emb, float* __restrict__ out)
{
    __shared__ float sC[FCHUNK * 66];
    const int cnt = g_cnt;
    if (blockIdx.x * 8 >= cnt) return;
    const int tid = threadIdx.x, warp = tid >> 5, lane = tid & 31;
    const int nwg = gridDim.x * 8;
    const int rounds = (cnt + nwg - 1) / nwg;
    for (int rd = 0; rd < rounds; rd++) {
        const int it = rd * nwg + blockIdx.x * 8 + warp;
        const bool act = it < cnt;
        const int n = act ? g_list[it] : 0;
        float xv[64];
        float Av = 0.f;
        if (act) {
            const float4* xr = (const float4*)(xg + (size_t)n * D);
            #pragma unroll
            for (int j = 0; j < 16; j++) {
                float4 v = xr[j];
                xv[4*j] = v.x; xv[4*j+1] = v.y; xv[4*j+2] = v.z; xv[4*j+3] = v.w;
            }
            #pragma unroll
            for (int d = 0; d < D; d++) Av = fmaf(xv[d], xv[d], Av);
        }
        float best = CUDART_INF_F; int bidx = 0;
        for (int ch = 0; ch < K / FCHUNK; ch++) {
            __syncthreads();
            const float4* e4 = (const float4*)(emb + (size_t)ch * FCHUNK * D);
            for (int i = tid; i < FCHUNK * 16; i += 256) {
                float4 v = e4[i];
                int row = i >> 4, j = i & 15;
                float* p = sC + row * 66 + j * 4;
                ((float2*)p)[0] = make_float2(v.x, v.y);
                ((float2*)p)[1] = make_float2(v.z, v.w);
            }
            __syncthreads();
            if (act) {
                for (int cj = 0; cj < FCHUNK / 32; cj++) {
                    int c = lane + cj * 32;
                    int k = ch * FCHUNK + c;
                    const float2* er = (const float2*)(sC + c * 66);
                    float a = 0.f;
                    #pragma unroll
                    for (int j = 0; j < 32; j++) {
                        float2 v = er[j];
                        a = fmaf(xv[2*j],   v.x, a);
                        a = fmaf(xv[2*j+1], v.y, a);
                    }
                    float ddv = (Av + g_B[k]) - 2.f * a;
                    if (ddv < best) { best = ddv; bidx = k; }
                }
            }
        }
        if (act) {
            unsigned long long key =
                ((unsigned long long)__float_as_uint(best) << 32) | (unsigned)bidx;
            #pragma unroll
            for (int o = 16; o; o >>= 1) {
                unsigned long long k2 = __shfl_down_sync(0xffffffffu, key, o);
                if (k2 < key) key = k2;
            }
            key = __shfl_sync(0xffffffffu, key, 0);
            int idx = (int)(key & 0xffffffffu);
            int old = g_idx[n];
            if (idx != old) {
                float lsn = 0.f, lso = 0.f;
                if (lane < 16) {
                    float4 e4 = ((const float4*)(emb + (size_t)idx * D))[lane];
                    float4 o4 = ((const float4*)(emb + (size_t)old * D))[lane];
                    float xx = xv[4*lane], xy = xv[4*lane+1], xz = xv[4*lane+2], xw2 = xv[4*lane+3];
                    float dx = e4.x-xx, dy = e4.y-xy, dz = e4.z-xz, dw = e4.w-xw2;
                    ((float4*)(out + (size_t)n * D))[lane] =
                        make_float4(xx+dx, xy+dy, xz+dz, xw2+dw);
                    lsn = dx*dx + dy*dy + dz*dz + dw*dw;
                    float ox = o4.x-xx, oy = o4.y-xy, oz = o4.z-xz, ow = o4.w-xw2;
                    lso = ox*ox + oy*oy + oz*oz + ow*ow;
                }
                #pragma unroll
                for (int o = 16; o; o >>= 1) {
                    lsn += __shfl_down_sync(0xffffffffu, lsn, o);
                    lso += __shfl_down_sync(0xffffffffu, lso, o);
                }
                if (lane == 0) atomicAdd(&g_fix, lsn - lso);
                float* er = out + OUT_E_OFF + (size_t)n * K;
                for (int c4 = lane; c4 < 256; c4 += 32) {
                    float4 v = make_float4(0.f, 0.f, 0.f, 0.f);
                    if ((idx >> 2) == c4) ((float*)&v)[idx & 3] = 1.f;
                    ((float4*)er)[c4] = v;
                }
            }
        }
    }
}

// ---------------- finalize: 128 partials + fix ----------------------------
__global__ void vq_finalize(float* __restrict__ out) {
    __shared__ double sR[128];
    int tid = threadIdx.x;   // 128
    sR[tid] = (double)g_part[tid];
    __syncthreads();
    #pragma unroll
    for (int st = 64; st; st >>= 1) {
        if (tid < st) sR[tid] += sR[tid + st];
        __syncthreads();
    }
    if (tid == 0) {
        double tot = sR[0] + (double)g_fix;
        float cb = (float)(tot / (double)((size_t)N_VEC * D));
        out[OUT_S_OFF + 0] = cb + 0.25f * cb;
        out[OUT_S_OFF + 1] = cb;
        out[OUT_S_OFF + 2] = cb;
    }
}

extern "C" void kernel_launch(void* const* d_in, const int* in_sizes, int n_in,
                              void* d_out, int out_size) {
    const float* x   = (const float*)d_in[0];
    const float* emb = (const float*)d_in[1];
    float* out = (float*)d_out;
    cudaFuncSetAttribute(vq_main, cudaFuncAttributeMaxDynamicSharedMemorySize, SMEM_TOTAL);
    vq_prep<<<8, 128>>>(emb);
    vq_main<<<NBLK, 512, SMEM_TOTAL>>>(x, emb, out);
    vq_fallback<<<148, 256>>>(x, emb, out);
    vq_finalize<<<1, 128>>>(out);
}

// round 6
// speedup vs baseline: 2.4164x; 1.0777x over previous
#include <cuda_runtime.h>
#include <cuda_bf16.h>
#include <cstdint>
#include <math_constants.h>

#define N_VEC 65536
#define D 64
#define K 1024
#define MTILE 512
#define NBLK (N_VEC / MTILE)       // 128
#define MARGIN 4e-4f
#define OUT_E_OFF ((size_t)N_VEC * D)
#define OUT_S_OFF (OUT_E_OFF + (size_t)N_VEC * K)

#define APAD 72                    // bf16 elems per padded row (144B)
#define BPAD 72
// dynamic smem offsets (bytes)
#define OFF_SB  0                  // 4KB : g_B copy
#define OFF_IDX 4096               // 2KB : per-row argmin
#define OFF_RED 6144               // 64B : per-warp loss partials
#define OFF_A   6272               // 512*144 = 73728
#define OFF_B   80000              // 1024*144 = 147456
#define SMEM_TOTAL 227456

__device__ float  g_B[K];
__device__ __align__(16) __nv_bfloat16 g_ebf[K * BPAD];
__device__ int    g_cnt;
__device__ int    g_list[N_VEC];
__device__ int    g_idx[N_VEC];
__device__ float  g_part[NBLK];
__device__ float  g_fix;

// descending top-4 insert (S[0] best). strict > keeps earlier (lower-k) on ties.
#define INS4(S, I, s, i) { if ((s) > S[3]) { \
    if ((s) > S[2]) { S[3]=S[2]; I[3]=I[2]; \
        if ((s) > S[1]) { S[2]=S[1]; I[2]=I[1]; \
            if ((s) > S[0]) { S[1]=S[0]; I[1]=I[0]; S[0]=(s); I[0]=(i); } \
            else { S[1]=(s); I[1]=(i); } } \
        else { S[2]=(s); I[2]=(i); } } \
    else { S[3]=(s); I[3]=(i); } } }

#define MMA(c, a, bb0, bb1) asm volatile( \
    "mma.sync.aligned.m16n8k16.row.col.f32.bf16.bf16.f32 " \
    "{%0,%1,%2,%3}, {%4,%5,%6,%7}, {%8,%9}, {%0,%1,%2,%3};" \
    : "+f"(c[0]), "+f"(c[1]), "+f"(c[2]), "+f"(c[3]) \
    : "r"(a[0]), "r"(a[1]), "r"(a[2]), "r"(a[3]), "r"(bb0), "r"(bb1))

#define CSWP(a, b) { if ((a) > (b)) { int _t = (a); (a) = (b); (b) = _t; } }

// ---------------- prep: g_B (exact chain) + padded bf16 codebook ----------
__global__ void vq_prep(const float* __restrict__ emb) {
    int k = blockIdx.x * blockDim.x + threadIdx.x;    // 8 x 128 = 1024
    float v[D];
    const float4* r4 = (const float4*)(emb + (size_t)k * D);
    #pragma unroll
    for (int j = 0; j < 16; j++) {
        float4 t = r4[j];
        v[4*j] = t.x; v[4*j+1] = t.y; v[4*j+2] = t.z; v[4*j+3] = t.w;
    }
    float bb = 0.f;
    #pragma unroll
    for (int d = 0; d < D; d++) bb += v[d] * v[d];
    g_B[k] = bb;
    __nv_bfloat162* eb = (__nv_bfloat162*)(g_ebf + (size_t)k * BPAD);
    #pragma unroll
    for (int j = 0; j < 32; j++)
        eb[j] = __float22bfloat162_rn(make_float2(v[2*j], v[2*j+1]));
    #pragma unroll
    for (int j = 32; j < 36; j++)
        eb[j] = __float22bfloat162_rn(make_float2(0.f, 0.f));
    if (k == 0) { g_cnt = 0; g_fix = 0.f; }
}

// ---------------- main: HMMA prefilter + top4 + exact rescore -------------
__global__ __launch_bounds__(512, 1) void vq_main(
    const float* __restrict__ xg, const float* __restrict__ emb, float* __restrict__ out)
{
    extern __shared__ char sm[];
    float*    sB   = (float*)(sm + OFF_SB);
    int*      sIdx = (int*)(sm + OFF_IDX);
    float*    sW   = (float*)(sm + OFF_RED);
    uint32_t* Aw   = (uint32_t*)(sm + OFF_A);   // 36 words per padded row
    uint32_t* Bw   = (uint32_t*)(sm + OFF_B);

    const int tid = threadIdx.x;
    const int warp = tid >> 5, lane = tid & 31;
    const int g = lane >> 2, tig = lane & 3;
    const int n0 = blockIdx.x * MTILE;

    for (int i = tid; i < K; i += 512) sB[i] = g_B[i];
    { // stage A: x f32 -> bf16 padded rows
        const float4* x4 = (const float4*)(xg + (size_t)n0 * D);
        for (int i = tid; i < MTILE * 16; i += 512) {
            float4 v = x4[i];
            int row = i >> 4, j = i & 15;
            __nv_bfloat162* p =
                (__nv_bfloat162*)((__nv_bfloat16*)(sm + OFF_A) + row * APAD + j * 4);
            p[0] = __float22bfloat162_rn(make_float2(v.x, v.y));
            p[1] = __float22bfloat162_rn(make_float2(v.z, v.w));
        }
    }
    { // stage B: padded bf16 codebook copy
        const float4* e4 = (const float4*)g_ebf;
        float4* s4 = (float4*)(sm + OFF_B);
        for (int i = tid; i < (K * BPAD * 2) / 16; i += 512) s4[i] = e4[i];
    }
    __syncthreads();

    const int rbase = warp * 32;
    // preload A fragments: [rowtile][kstep][4 regs]
    uint32_t af[2][4][4];
    #pragma unroll
    for (int rt = 0; rt < 2; rt++) {
        int r0w = (rbase + rt * 16 + g) * 36;
        #pragma unroll
        for (int ks = 0; ks < 4; ks++) {
            int kw = ks * 8 + tig;
            af[rt][ks][0] = Aw[r0w + kw];
            af[rt][ks][1] = Aw[r0w + 288 + kw];      // +8 rows
            af[rt][ks][2] = Aw[r0w + kw + 4];
            af[rt][ks][3] = Aw[r0w + 288 + kw + 4];
        }
    }
    float TS[4][4]; int TI[4][4];
    #pragma unroll
    for (int j = 0; j < 4; j++)
        #pragma unroll
        for (int p = 0; p < 4; p++) { TS[j][p] = -CUDART_INF_F; TI[j][p] = 0; }

    for (int nt = 0; nt < 128; nt++) {
        const int nbase = nt * 8;
        uint32_t b0[4], b1[4];
        const int brw = (nbase + g) * 36;
        #pragma unroll
        for (int ks = 0; ks < 4; ks++) {
            b0[ks] = Bw[brw + ks * 8 + tig];
            b1[ks] = Bw[brw + ks * 8 + tig + 4];
        }
        float c0[4] = {0.f,0.f,0.f,0.f}, c1[4] = {0.f,0.f,0.f,0.f};
        #pragma unroll
        for (int ks = 0; ks < 4; ks++) {
            MMA(c0, af[0][ks], b0[ks], b1[ks]);
            MMA(c1, af[1][ks], b0[ks], b1[ks]);
        }
        const int k0i = nbase + tig * 2;
        const float Bc0 = sB[k0i], Bc1 = sB[k0i + 1];
        // scores (proxy = 2*dot - ||e||^2); gated inserts (gate skips only no-ops)
        {
            float sa = fmaf(2.f, c0[0], -Bc0), sb2 = fmaf(2.f, c0[1], -Bc1);
            if (fmaxf(sa, sb2) > TS[0][3]) { INS4(TS[0], TI[0], sa, k0i); INS4(TS[0], TI[0], sb2, k0i+1); }
        }
        {
            float sa = fmaf(2.f, c0[2], -Bc0), sb2 = fmaf(2.f, c0[3], -Bc1);
            if (fmaxf(sa, sb2) > TS[1][3]) { INS4(TS[1], TI[1], sa, k0i); INS4(TS[1], TI[1], sb2, k0i+1); }
        }
        {
            float sa = fmaf(2.f, c1[0], -Bc0), sb2 = fmaf(2.f, c1[1], -Bc1);
            if (fmaxf(sa, sb2) > TS[2][3]) { INS4(TS[2], TI[2], sa, k0i); INS4(TS[2], TI[2], sb2, k0i+1); }
        }
        {
            float sa = fmaf(2.f, c1[2], -Bc0), sb2 = fmaf(2.f, c1[3], -Bc1);
            if (fmaxf(sa, sb2) > TS[3][3]) { INS4(TS[3], TI[3], sa, k0i); INS4(TS[3], TI[3], sb2, k0i+1); }
        }
    }
    // quad merge (lanes in a quad own the same 4 rows, disjoint cols)
    #pragma unroll
    for (int dd = 1; dd <= 2; dd <<= 1) {
        #pragma unroll
        for (int j = 0; j < 4; j++) {
            float ns[4]; int ni[4];
            #pragma unroll
            for (int p = 0; p < 4; p++) {
                ns[p] = __shfl_xor_sync(0xffffffffu, TS[j][p], dd);
                ni[p] = __shfl_xor_sync(0xffffffffu, TI[j][p], dd);
            }
            #pragma unroll
            for (int p = 0; p < 4; p++) INS4(TS[j], TI[j], ns[p], ni[p]);
        }
    }
    // this thread owns row slot j == tig  (row = g + tig*8 within warp)
    const int rowp = rbase + g + tig * 8;
    const int n = n0 + rowp;
    float cs[4]; int ci[4];
    #pragma unroll
    for (int j = 0; j < 4; j++) if (tig == j) {
        #pragma unroll
        for (int p = 0; p < 4; p++) { cs[p] = TS[j][p]; ci[p] = TI[j][p]; }
    }
    const bool fb = (cs[3] >= cs[0] - MARGIN);
    CSWP(ci[0], ci[1]); CSWP(ci[2], ci[3]);
    CSWP(ci[0], ci[2]); CSWP(ci[1], ci[3]); CSWP(ci[1], ci[2]);

    // exact rescore (validated round-0 fl chain, ascending-k strict <)
    float xv[64];
    {
        const float4* xr = (const float4*)(xg + (size_t)n * D);
        #pragma unroll
        for (int j = 0; j < 16; j++) {
            float4 v = xr[j];
            xv[4*j] = v.x; xv[4*j+1] = v.y; xv[4*j+2] = v.z; xv[4*j+3] = v.w;
        }
    }
    float Av = 0.f;
    #pragma unroll
    for (int d = 0; d < D; d++) Av = fmaf(xv[d], xv[d], Av);
    float best = CUDART_INF_F; int bidx = 0;
    #pragma unroll
    for (int q = 0; q < 4; q++) {
        int idx = ci[q];
        const float4* er = (const float4*)(emb + (size_t)idx * D);
        float a = 0.f;
        #pragma unroll
        for (int j = 0; j < 16; j++) {
            float4 v = er[j];
            a = fmaf(xv[4*j],   v.x, a);
            a = fmaf(xv[4*j+1], v.y, a);
            a = fmaf(xv[4*j+2], v.z, a);
            a = fmaf(xv[4*j+3], v.w, a);
        }
        float ddv = (Av + sB[idx]) - 2.f * a;
        if (ddv < best) { best = ddv; bidx = idx; }
    }
    if (fb) { int sl = atomicAdd(&g_cnt, 1); g_list[sl] = n; }
    sIdx[rowp] = bidx;
    __syncthreads();

    // g_idx coalesced
    g_idx[n0 + tid] = sIdx[tid];

    // quantized_st + per-vector loss: LINEAR coalesced loop (L2-friendly)
    float ls = 0.f;
    {
        const float4* x4 = (const float4*)(xg + (size_t)n0 * D);
        float4* qo = (float4*)(out + (size_t)n0 * D);
        #pragma unroll
        for (int it = 0; it < 16; it++) {
            int i = tid + it * 512;
            int r = i >> 4, c4 = i & 15;
            int idx = sIdx[r];
            float4 xw = x4[i];
            float4 e4 = ((const float4*)(emb + (size_t)idx * D))[c4];
            float dx = e4.x - xw.x, dy = e4.y - xw.y;
            float dz = e4.z - xw.z, dw = e4.w - xw.w;
            float4 o4 = make_float4(xw.x + dx, xw.y + dy, xw.z + dz, xw.w + dw);
            __stcs(&qo[i], o4);
            ls += dx*dx + dy*dy + dz*dz + dw*dw;
        }
    }
    // block loss reduction: intra-warp shfl, then warp leaders
    #pragma unroll
    for (int o = 16; o; o >>= 1) ls += __shfl_down_sync(0xffffffffu, ls, o);
    if (lane == 0) sW[warp] = ls;
    __syncthreads();
    if (tid == 0) {
        float s = 0.f;
        #pragma unroll
        for (int w = 0; w < 16; w++) s += sW[w];
        g_part[blockIdx.x] = s;
    }
}

// ---------------- one-hot encodings: dedicated streaming kernel -----------
__global__ __launch_bounds__(256) void vq_onehot(float* __restrict__ out) {
    __shared__ int sI[32];
    const int r0 = blockIdx.x * 32;       // grid 2048
    if (threadIdx.x < 32) sI[threadIdx.x] = g_idx[r0 + threadIdx.x];
    __syncthreads();
    float* eout = out + OUT_E_OFF;
    #pragma unroll 4
    for (int i = threadIdx.x; i < 32 * 256; i += 256) {
        int r = i >> 8, c4 = i & 255;
        int idx = sI[r];
        float4 v = make_float4(0.f, 0.f, 0.f, 0.f);
        if ((idx >> 2) == c4) ((float*)&v)[idx & 3] = 1.f;
        __stcs(&((float4*)(eout + (size_t)(r0 + r) * K))[c4], v);
    }
}

// ---------------- fallback: exact full scan, chunked smem codebook --------
#define FCHUNK 128
__global__ __launch_bounds__(256) void vq_fallback(
    const float* __restrict__ xg, const float* __restrict__ emb, float* __restrict__ out)
{
    __shared__ float sC[FCHUNK * 66];
    const int cnt = g_cnt;
    if (blockIdx.x * 8 >= cnt) return;
    const int tid = threadIdx.x, warp = tid >> 5, lane = tid & 31;
    const int nwg = gridDim.x * 8;
    const int rounds = (cnt + nwg - 1) / nwg;
    for (int rd = 0; rd < rounds; rd++) {
        const int it = rd * nwg + blockIdx.x * 8 + warp;
        const bool act = it < cnt;
        const int n = act ? g_list[it] : 0;
        float xv[64];
        float Av = 0.f;
        if (act) {
            const float4* xr = (const float4*)(xg + (size_t)n * D);
            #pragma unroll
            for (int j = 0; j < 16; j++) {
                float4 v = xr[j];
                xv[4*j] = v.x; xv[4*j+1] = v.y; xv[4*j+2] = v.z; xv[4*j+3] = v.w;
            }
            #pragma unroll
            for (int d = 0; d < D; d++) Av = fmaf(xv[d], xv[d], Av);
        }
        float best = CUDART_INF_F; int bidx = 0;
        for (int ch = 0; ch < K / FCHUNK; ch++) {
            __syncthreads();
            const float4* e4 = (const float4*)(emb + (size_t)ch * FCHUNK * D);
            for (int i = tid; i < FCHUNK * 16; i += 256) {
                float4 v = e4[i];
                int row = i >> 4, j = i & 15;
                float* p = sC + row * 66 + j * 4;
                ((float2*)p)[0] = make_float2(v.x, v.y);
                ((float2*)p)[1] = make_float2(v.z, v.w);
            }
            __syncthreads();
            if (act) {
                for (int cj = 0; cj < FCHUNK / 32; cj++) {
                    int c = lane + cj * 32;
                    int k = ch * FCHUNK + c;
                    const float2* er = (const float2*)(sC + c * 66);
                    float a = 0.f;
                    #pragma unroll
                    for (int j = 0; j < 32; j++) {
                        float2 v = er[j];
                        a = fmaf(xv[2*j],   v.x, a);
                        a = fmaf(xv[2*j+1], v.y, a);
                    }
                    float ddv = (Av + g_B[k]) - 2.f * a;
                    if (ddv < best) { best = ddv; bidx = k; }
                }
            }
        }
        if (act) {
            unsigned long long key =
                ((unsigned long long)__float_as_uint(best) << 32) | (unsigned)bidx;
            #pragma unroll
            for (int o = 16; o; o >>= 1) {
                unsigned long long k2 = __shfl_down_sync(0xffffffffu, key, o);
                if (k2 < key) key = k2;
            }
            key = __shfl_sync(0xffffffffu, key, 0);
            int idx = (int)(key & 0xffffffffu);
            int old = g_idx[n];
            if (idx != old) {
                float lsn = 0.f, lso = 0.f;
                if (lane < 16) {
                    float4 e4 = ((const float4*)(emb + (size_t)idx * D))[lane];
                    float4 o4 = ((const float4*)(emb + (size_t)old * D))[lane];
                    float xx = xv[4*lane], xy = xv[4*lane+1], xz = xv[4*lane+2], xw2 = xv[4*lane+3];
                    float dx = e4.x-xx, dy = e4.y-xy, dz = e4.z-xz, dw = e4.w-xw2;
                    ((float4*)(out + (size_t)n * D))[lane] =
                        make_float4(xx+dx, xy+dy, xz+dz, xw2+dw);
                    lsn = dx*dx + dy*dy + dz*dz + dw*dw;
                    float ox = o4.x-xx, oy = o4.y-xy, oz = o4.z-xz, ow = o4.w-xw2;
                    lso = ox*ox + oy*oy + oz*oz + ow*ow;
                }
                #pragma unroll
                for (int o = 16; o; o >>= 1) {
                    lsn += __shfl_down_sync(0xffffffffu, lsn, o);
                    lso += __shfl_down_sync(0xffffffffu, lso, o);
                }
                if (lane == 0) atomicAdd(&g_fix, lsn - lso);
                float* er = out + OUT_E_OFF + (size_t)n * K;
                for (int c4 = lane; c4 < 256; c4 += 32) {
                    float4 v = make_float4(0.f, 0.f, 0.f, 0.f);
                    if ((idx >> 2) == c4) ((float*)&v)[idx & 3] = 1.f;
                    ((float4*)er)[c4] = v;
                }
            }
        }
    }
}

// ---------------- finalize: 128 partials + fix ----------------------------
__global__ void vq_finalize(float* __restrict__ out) {
    __shared__ double sR[128];
    int tid = threadIdx.x;   // 128
    sR[tid] = (double)g_part[tid];
    __syncthreads();
    #pragma unroll
    for (int st = 64; st; st >>= 1) {
        if (tid < st) sR[tid] += sR[tid + st];
        __syncthreads();
    }
    if (tid == 0) {
        double tot = sR[0] + (double)g_fix;
        float cb = (float)(tot / (double)((size_t)N_VEC * D));
        out[OUT_S_OFF + 0] = cb + 0.25f * cb;
        out[OUT_S_OFF + 1] = cb;
        out[OUT_S_OFF + 2] = cb;
    }
}

extern "C" void kernel_launch(void* const* d_in, const int* in_sizes, int n_in,
                              void* d_out, int out_size) {
    const float* x   = (const float*)d_in[0];
    const float* emb = (const float*)d_in[1];
    float* out = (float*)d_out;
    cudaFuncSetAttribute(vq_main, cudaFuncAttributeMaxDynamicSharedMemorySize, SMEM_TOTAL);
    vq_prep<<<8, 128>>>(emb);
    vq_main<<<NBLK, 512, SMEM_TOTAL>>>(x, emb, out);
    vq_onehot<<<N_VEC / 32, 256>>>(out);
    vq_fallback<<<148, 256>>>(x, emb, out);
    vq_finalize<<<1, 128>>>(out);
}